// round 13
// baseline (speedup 1.0000x reference)
#include <cuda_runtime.h>
#include <cuda_bf16.h>
#include <cstdint>

// ---------------------------------------------------------------------------
// SphereVoxelConv: DeepSphere U-Net forward.
// Round 13: exact round-10 configuration (measured 1528us) with one change:
// bn_finalize folded into bn_apply (per-block smem recompute) -- removes 8
// launches from the serial chain. fp32 BN, fused bf16-split emission,
// tcgen05 bf16 2-term split GEMMs, CSR SpMM L-applies, Clenshaw decoder.
// ---------------------------------------------------------------------------

#if defined(__CUDA_ARCH_FEAT_SM103_ALL) || defined(__CUDA_ARCH_FEAT_SM100_ALL) || defined(__CUDA_ARCH_FEAT_SM101_ALL)
#define HAS_TCGEN05 1
#else
#define HAS_TCGEN05 0
#endif

#define BATCH 256            // B*H*W = 4*8*8
constexpr int N3 = 768, N2 = 192, N1 = 48, N0 = 12;
constexpr int R3r = N3 * BATCH;   // 196608
constexpr int R2r = N2 * BATCH;   // 49152
constexpr int R1r = N1 * BATCH;   // 12288
constexpr int R0r = N0 * BATCH;   // 3072

// ---- static fp32 scratch pool ----
constexpr size_t SZ_S3 = (size_t)R3r * 64;
constexpr size_t SZ_S2 = (size_t)R2r * 128;
constexpr size_t SZ_S1 = (size_t)R1r * 256;
constexpr size_t SZ_XA = (size_t)R3r * 32;
constexpr size_t SZ_XB = (size_t)R3r * 128;
constexpr size_t SZ_X2 = (size_t)R2r * 256;
constexpr size_t SZ_X1 = (size_t)R1r * 512;
constexpr size_t SZ_X0 = (size_t)R0r * 1024;
constexpr size_t SZ_T  = (size_t)R3r * 32;
constexpr size_t SZ_U  = (size_t)R3r * 4;

constexpr size_t OFF_S3 = 0;
constexpr size_t OFF_S2 = OFF_S3 + SZ_S3;
constexpr size_t OFF_S1 = OFF_S2 + SZ_S2;
constexpr size_t OFF_XA = OFF_S1 + SZ_S1;
constexpr size_t OFF_XB = OFF_XA + SZ_XA;
constexpr size_t OFF_X2 = OFF_XB + SZ_XB;
constexpr size_t OFF_X1 = OFF_X2 + SZ_X2;
constexpr size_t OFF_X0 = OFF_X1 + SZ_X1;
constexpr size_t OFF_T0 = OFF_X0 + SZ_X0;
constexpr size_t OFF_T1 = OFF_T0 + SZ_T;
constexpr size_t OFF_T2 = OFF_T1 + SZ_T;
constexpr size_t OFF_T3 = OFF_T2 + SZ_T;
constexpr size_t OFF_U  = OFF_T3 + SZ_T;
constexpr size_t OFF_W  = OFF_U + SZ_U;
constexpr size_t SZ_W   = 512 * 512;
constexpr size_t POOL_TOTAL = OFF_W + SZ_W;

__device__ __align__(256) float g_pool[POOL_TOTAL];
__device__ float g_stats[4096];   // 8 regions of 512 (sum / sumsq)

constexpr size_t BF_MAX = (size_t)R3r * 128;
__device__ __align__(256) __nv_bfloat16 g_ahi[BF_MAX];
__device__ __align__(256) __nv_bfloat16 g_alo[BF_MAX];
__device__ __align__(256) __nv_bfloat16 g_bp[1 << 20];

constexpr int C3 = N3 * N3, C2 = N2 * N2, C1 = N1 * N1, C0 = N0 * N0;
__device__ int   g_ccols[C3 + C2 + C1 + C0];
__device__ float g_cvals[C3 + C2 + C1 + C0];
__device__ int   g_cnnz[N3 + N2 + N1 + N0];

static inline int cdiv(long a, long b) { return (int)((a + b - 1) / b); }

// ---------------------------------------------------------------------------
// PTX helpers
// ---------------------------------------------------------------------------
__device__ __forceinline__ uint32_t smem_u32(const void* p) {
    uint32_t a;
    asm("{ .reg .u64 t; cvta.to.shared.u64 t, %1; cvt.u32.u64 %0, t; }"
        : "=r"(a) : "l"(p));
    return a;
}

#if HAS_TCGEN05
__device__ __forceinline__ uint32_t elect1() {
    uint32_t p;
    asm volatile("{ .reg .pred p; elect.sync _|p, 0xFFFFFFFF; selp.b32 %0,1,0,p; }"
                 : "=r"(p));
    return p;
}

__device__ __forceinline__ void mb_init(uint32_t addr, uint32_t cnt) {
    asm volatile("mbarrier.init.shared.b64 [%0], %1;" :: "r"(addr), "r"(cnt) : "memory");
}

__device__ __forceinline__ void mb_wait(uint32_t addr, uint32_t par) {
    asm volatile(
        "{\n\t"
        ".reg .pred P1;\n\t"
        "WAIT_%=:\n\t"
        "mbarrier.try_wait.parity.acquire.cta.shared::cta.b64 P1, [%0], %1, 0x989680;\n\t"
        "@P1 bra.uni DONE_%=;\n\t"
        "bra.uni WAIT_%=;\n\t"
        "DONE_%=:\n\t"
        "}"
        :: "r"(addr), "r"(par) : "memory");
}

__device__ __forceinline__ void tc_ld16(uint32_t* r, uint32_t ta) {
    asm volatile(
        "tcgen05.ld.sync.aligned.32x32b.x16.b32 "
        "{%0,%1,%2,%3,%4,%5,%6,%7,%8,%9,%10,%11,%12,%13,%14,%15}, [%16];"
        : "=r"(r[0]), "=r"(r[1]), "=r"(r[2]), "=r"(r[3]),
          "=r"(r[4]), "=r"(r[5]), "=r"(r[6]), "=r"(r[7]),
          "=r"(r[8]), "=r"(r[9]), "=r"(r[10]), "=r"(r[11]),
          "=r"(r[12]), "=r"(r[13]), "=r"(r[14]), "=r"(r[15])
        : "r"(ta));
}
#endif  // HAS_TCGEN05

constexpr uint64_t DESC_BASE =
    (uint64_t(2) << 61) | (uint64_t(1) << 46) | (uint64_t(64) << 32) | (uint64_t(1) << 16);

// ---------------------------------------------------------------------------
// Tile loaders (SW128): A segments along K' are [Ahi | Ahi | Alo]
// ---------------------------------------------------------------------------
__device__ __forceinline__ void load_tile_A(char* smem, int off,
    const __nv_bfloat16* __restrict__ Ahi, const __nv_bfloat16* __restrict__ Alo,
    int rowBase, int K, int K3, int twoK, int q0, int tid) {
#pragma unroll
    for (int i = 0; i < 8; i++) {
        int g = tid + i * 128;
        int r = g >> 3, c = (g & 7) * 8;
        int kq = q0 + c;
        uint4 v = make_uint4(0u, 0u, 0u, 0u);
        if (kq < K3) {
            const __nv_bfloat16* src = (kq >= twoK) ? Alo : Ahi;
            int k = kq;
            if (k >= twoK) k -= twoK; else if (k >= K) k -= K;
            v = *(const uint4*)(src + (size_t)(rowBase + r) * K + k);
        }
        uint32_t bo = (uint32_t)(r * 128 + c * 2);
        *(uint4*)(smem + off + (bo ^ ((bo >> 3) & 0x70))) = v;
    }
}

template<int BN>
__device__ __forceinline__ void load_tile_B(char* smem, int off,
    const __nv_bfloat16* __restrict__ Bp,
    int colBase, int K3, int q0, int tid) {
    constexpr int BG = BN * 8 / 128;
#pragma unroll
    for (int i = 0; i < BG; i++) {
        int g = tid + i * 128;
        int r = g >> 3, c = (g & 7) * 8;
        int kq = q0 + c;
        uint4 v = make_uint4(0u, 0u, 0u, 0u);
        if (kq < K3)
            v = *(const uint4*)(Bp + (size_t)(colBase + r) * K3 + kq);
        uint32_t bo = (uint32_t)(r * 128 + c * 2);
        *(uint4*)(smem + off + (bo ^ ((bo >> 3) & 0x70))) = v;
    }
}

// ---------------------------------------------------------------------------
// GEMM: C(MxN) = splitA(MxK) * Bp(Nx3K), fp32 out.
// ---------------------------------------------------------------------------
template<int BN>
__global__ __launch_bounds__(128)
void tc_gemm(int M, int Ntot, int K, int K3,
             const __nv_bfloat16* __restrict__ Ahi,
             const __nv_bfloat16* __restrict__ Alo,
             const __nv_bfloat16* __restrict__ Bp,
             float* __restrict__ C, int ldc,
             int split, float* __restrict__ o0, float* __restrict__ o1,
             float* __restrict__ o2, float* __restrict__ o3)
{
#if HAS_TCGEN05
    extern __shared__ char smem[];
    const int tid = threadIdx.x;
    const int wid = tid >> 5;
    const int lane = tid & 31;
    const int rowBase = blockIdx.y * 128;
    const int colBase = blockIdx.x * BN;

    const uint32_t sbase = smem_u32(smem);
    const uint32_t hdr = sbase;                  // [0] tmem ptr, [8],[16] mbarriers
    const uint32_t tbase = (sbase + 1024 + 1023) & ~1023u;
    const int tchar = (int)(tbase - sbase);
    constexpr int ABYTES = 128 * 128;
    constexpr int BBYTES = BN * 128;
    const int offA0 = tchar;
    const int offB0 = tchar + ABYTES;
    const int offA1 = tchar + ABYTES + BBYTES;
    const int offB1 = tchar + 2 * ABYTES + BBYTES;
    constexpr uint32_t TCOLS = (BN < 32) ? 32u : (uint32_t)BN;

    if (tid == 0) { mb_init(hdr + 8, 1); mb_init(hdr + 16, 1); }
    if (wid == 0) {
        asm volatile("tcgen05.alloc.cta_group::1.sync.aligned.shared::cta.b32 [%0], %1;"
                     :: "r"(hdr), "r"(TCOLS) : "memory");
        asm volatile("tcgen05.relinquish_alloc_permit.cta_group::1.sync.aligned;");
    }
    __syncthreads();
    uint32_t tmem;
    asm volatile("ld.shared.b32 %0, [%1];" : "=r"(tmem) : "r"(hdr));

    const uint32_t idesc = 0x490u | ((uint32_t)(BN / 8) << 17) | (8u << 24);
    const int nch = (K3 + 63) >> 6;
    const int twoK = 2 * K;

    load_tile_A(smem, offA0, Ahi, Alo, rowBase, K, K3, twoK, 0, tid);
    load_tile_B<BN>(smem, offB0, Bp, colBase, K3, 0, tid);
    asm volatile("fence.proxy.async.shared::cta;" ::: "memory");
    __syncthreads();

    int ph0 = 0, ph1 = 0;
    for (int ch = 0; ch < nch; ch++) {
        const int buf = ch & 1;
        const int offA = buf ? offA1 : offA0;
        const int offB = buf ? offB1 : offB0;
        if (wid == 0 && elect1()) {
            uint64_t da = DESC_BASE | (uint64_t)(((sbase + offA) >> 4) & 0x3FFF);
            uint64_t db = DESC_BASE | (uint64_t)(((sbase + offB) >> 4) & 0x3FFF);
#pragma unroll
            for (int s = 0; s < 4; s++) {
                uint32_t en = (ch > 0 || s > 0) ? 1u : 0u;
                asm volatile(
                    "{\n\t.reg .pred p;\n\tsetp.ne.u32 p, %5, 0;\n\t"
                    "tcgen05.mma.cta_group::1.kind::f16 [%0], %1, %2, %3, {%4, %4, %4, %4}, p;\n\t}"
                    :: "r"(tmem), "l"(da + s * 2), "l"(db + s * 2), "r"(idesc),
                       "r"(0u), "r"(en) : "memory");
            }
            asm volatile(
                "tcgen05.commit.cta_group::1.mbarrier::arrive::one.shared::cluster.b64 [%0];"
                :: "r"(hdr + 8 + 8 * buf) : "memory");
        }
        if (ch + 1 < nch) {
            if (ch >= 1) {
                if (((ch + 1) & 1) == 0) { mb_wait(hdr + 8, ph0); ph0 ^= 1; }
                else                     { mb_wait(hdr + 16, ph1); ph1 ^= 1; }
            }
            const int offAn = buf ? offA0 : offA1;
            const int offBn = buf ? offB0 : offB1;
            load_tile_A(smem, offAn, Ahi, Alo, rowBase, K, K3, twoK, (ch + 1) * 64, tid);
            load_tile_B<BN>(smem, offBn, Bp, colBase, K3, (ch + 1) * 64, tid);
            asm volatile("fence.proxy.async.shared::cta;" ::: "memory");
        }
        __syncthreads();
    }
    if (((nch - 1) & 1) == 0) mb_wait(hdr + 8, ph0);
    else                      mb_wait(hdr + 16, ph1);
    asm volatile("tcgen05.fence::after_thread_sync;" ::: "memory");

    // ---- epilogue ----
    const int gr = rowBase + wid * 32 + lane;
#pragma unroll 1
    for (int b0 = 0; b0 < BN; b0 += 32) {
        uint32_t r[32];
        tc_ld16(r, tmem + b0);
        tc_ld16(r + 16, tmem + b0 + 16);
        asm volatile("tcgen05.wait::ld.sync.aligned;" ::: "memory");
        if (split > 0) {
#pragma unroll
            for (int c = 0; c < 32; c += 4) {
                int gc = colBase + b0 + c;
                int p = gc / split, lc = gc - p * split;
                float* op = (p == 0) ? o0 : (p == 1) ? o1 : (p == 2) ? o2 : o3;
                float4 v = make_float4(__uint_as_float(r[c]), __uint_as_float(r[c + 1]),
                                       __uint_as_float(r[c + 2]), __uint_as_float(r[c + 3]));
                *(float4*)(op + (size_t)gr * split + lc) = v;
            }
        } else {
#pragma unroll
            for (int c = 0; c < 32; c += 4) {
                float4 v = make_float4(__uint_as_float(r[c]), __uint_as_float(r[c + 1]),
                                       __uint_as_float(r[c + 2]), __uint_as_float(r[c + 3]));
                *(float4*)(C + (size_t)gr * ldc + colBase + b0 + c) = v;
            }
        }
    }
    __syncthreads();
    if (wid == 0)
        asm volatile("tcgen05.dealloc.cta_group::1.sync.aligned.b32 %0, %1;"
                     :: "r"(tmem), "r"(TCOLS));
#else
    // -------- SIMT fallback (generic PTX pass; correct, slow) --------
    const int tid = threadIdx.x;
    const int rowBase = blockIdx.y * 128;
    const int colBase = blockIdx.x * BN;
    const int gr = rowBase + tid;
    const __nv_bfloat16* ah = Ahi + (size_t)gr * K;
    const __nv_bfloat16* al = Alo + (size_t)gr * K;
    for (int j0 = 0; j0 < BN; j0 += 8) {
        float acc[8];
#pragma unroll
        for (int j = 0; j < 8; j++) acc[j] = 0.f;
        for (int k = 0; k < K; k++) {
            float av = __bfloat162float(ah[k]);
            float lv = __bfloat162float(al[k]);
#pragma unroll
            for (int j = 0; j < 8; j++) {
                const __nv_bfloat16* b = Bp + (size_t)(colBase + j0 + j) * K3;
                float bh = __bfloat162float(b[k]);
                float bl = __bfloat162float(b[K + k]);
                acc[j] += av * bh + av * bl + lv * bh;
            }
        }
#pragma unroll
        for (int j = 0; j < 8; j++) {
            int gc = colBase + j0 + j;
            if (split > 0) {
                int p = gc / split, lc = gc - p * split;
                float* op = (p == 0) ? o0 : (p == 1) ? o1 : (p == 2) ? o2 : o3;
                op[(size_t)gr * split + lc] = acc[j];
            } else {
                C[(size_t)gr * ldc + gc] = acc[j];
            }
        }
    }
#endif
}

// ---------------------------------------------------------------------------
// CSR build (deterministic ballot-scan, 1 warp per row)
// ---------------------------------------------------------------------------
__global__ void build_csr_kernel(const float* __restrict__ L, int n,
                                 int* __restrict__ cols, float* __restrict__ vals,
                                 int* __restrict__ nnz) {
    int row = blockIdx.x * 8 + (threadIdx.x >> 5);
    if (row >= n) return;
    int lane = threadIdx.x & 31;
    unsigned lt = (1u << lane) - 1u;
    int cnt = 0;
    for (int c0 = 0; c0 < n; c0 += 32) {
        int c = c0 + lane;
        float v = (c < n) ? L[(long)row * n + c] : 0.f;
        unsigned m = __ballot_sync(0xffffffffu, v != 0.f);
        if (v != 0.f) {
            int pos = cnt + __popc(m & lt);
            cols[(long)row * n + pos] = c;
            vals[(long)row * n + pos] = v;
        }
        cnt += __popc(m);
    }
    if (lane == 0) nnz[row] = cnt;
}

// ---------------------------------------------------------------------------
// SpMM: out = alpha*(L in) + beta*cin, optional aux -= alpha*(L in),
// optional bf16 hi/lo emission of the final value (row stride Kb elements).
// ---------------------------------------------------------------------------
__global__ void spmm_kernel(int W4, int fshift, int fmask, int G4, long RS4,
                            float alpha, const float4* __restrict__ in,
                            float beta, const float4* __restrict__ cin,
                            float4* __restrict__ out, float4* __restrict__ aux,
                            __nv_bfloat16* __restrict__ hi,
                            __nv_bfloat16* __restrict__ lo, long Kb,
                            const int* __restrict__ cols,
                            const float* __restrict__ vals,
                            const int* __restrict__ nnz, int pitch) {
    __shared__ float sv[768];
    __shared__ int   sc[768];
    int node = blockIdx.y;
    int cnt = nnz[node];
    for (int j = threadIdx.x; j < cnt; j += blockDim.x) {
        sv[j] = vals[(long)node * pitch + j];
        sc[j] = cols[(long)node * pitch + j];
    }
    __syncthreads();
    int c4 = blockIdx.x * blockDim.x + threadIdx.x;
    if (c4 >= W4) return;
    int t  = c4 >> fshift;
    int f4 = c4 & fmask;
    long off = (long)t * G4 + f4;
    float4 acc = make_float4(0.f, 0.f, 0.f, 0.f);
    int j = 0;
    for (; j + 4 <= cnt; j += 4) {
        float v0 = sv[j], v1 = sv[j + 1], v2 = sv[j + 2], v3 = sv[j + 3];
        float4 x0 = in[(long)sc[j] * RS4 + off];
        float4 x1 = in[(long)sc[j + 1] * RS4 + off];
        float4 x2 = in[(long)sc[j + 2] * RS4 + off];
        float4 x3 = in[(long)sc[j + 3] * RS4 + off];
        acc.x = fmaf(v0, x0.x, acc.x); acc.y = fmaf(v0, x0.y, acc.y);
        acc.z = fmaf(v0, x0.z, acc.z); acc.w = fmaf(v0, x0.w, acc.w);
        acc.x = fmaf(v1, x1.x, acc.x); acc.y = fmaf(v1, x1.y, acc.y);
        acc.z = fmaf(v1, x1.z, acc.z); acc.w = fmaf(v1, x1.w, acc.w);
        acc.x = fmaf(v2, x2.x, acc.x); acc.y = fmaf(v2, x2.y, acc.y);
        acc.z = fmaf(v2, x2.z, acc.z); acc.w = fmaf(v2, x2.w, acc.w);
        acc.x = fmaf(v3, x3.x, acc.x); acc.y = fmaf(v3, x3.y, acc.y);
        acc.z = fmaf(v3, x3.z, acc.z); acc.w = fmaf(v3, x3.w, acc.w);
    }
    for (; j < cnt; j++) {
        float v0 = sv[j];
        float4 x0 = in[(long)sc[j] * RS4 + off];
        acc.x = fmaf(v0, x0.x, acc.x); acc.y = fmaf(v0, x0.y, acc.y);
        acc.z = fmaf(v0, x0.z, acc.z); acc.w = fmaf(v0, x0.w, acc.w);
    }
    acc.x *= alpha; acc.y *= alpha; acc.z *= alpha; acc.w *= alpha;
    long oidx = (long)node * RS4 + off;
    if (aux) {
        float4 a = aux[oidx];
        a.x -= acc.x; a.y -= acc.y; a.z -= acc.z; a.w -= acc.w;
        aux[oidx] = a;
    }
    if (beta != 0.f) {
        float4 ci = cin[oidx];
        acc.x = fmaf(beta, ci.x, acc.x); acc.y = fmaf(beta, ci.y, acc.y);
        acc.z = fmaf(beta, ci.z, acc.z); acc.w = fmaf(beta, ci.w, acc.w);
    }
    out[oidx] = acc;
    if (hi) {
        long e = ((long)node * BATCH + t) * Kb + 4 * f4;
        __nv_bfloat16 h[4], l[4];
        float vv[4] = { acc.x, acc.y, acc.z, acc.w };
#pragma unroll
        for (int q = 0; q < 4; q++) {
            h[q] = __float2bfloat16(vv[q]);
            l[q] = __float2bfloat16(vv[q] - __bfloat162float(h[q]));
        }
        *(uint2*)(hi + e) = *(uint2*)h;
        *(uint2*)(lo + e) = *(uint2*)l;
    }
}

struct Csr { const int* cols; const float* vals; const int* nnz; int pitch; };

static void run_spmm(const Csr& cs, int nodes, int W, int Fin, int G, int RS,
                     float alpha, const float* in, float beta, const float* cin,
                     float* out, float* aux,
                     __nv_bfloat16* hi = nullptr, __nv_bfloat16* lo = nullptr,
                     long Kb = 0) {
    int W4 = W / 4;
    int f4 = Fin / 4;
    int fshift = 0; while ((1 << fshift) < f4) fshift++;
    int fmask = f4 - 1;
    dim3 grid(cdiv(W4, 256), nodes);
    spmm_kernel<<<grid, 256>>>(W4, fshift, fmask, G / 4, (long)(RS / 4), alpha,
                               (const float4*)in, beta, (const float4*)cin,
                               (float4*)out, (float4*)aux, hi, lo, Kb,
                               cs.cols, cs.vals, cs.nnz, cs.pitch);
}

// ---------------------------------------------------------------------------
// Elementwise kernels
// ---------------------------------------------------------------------------
__global__ void permute_in_kernel(const float* __restrict__ x, float* __restrict__ out,
                                  __nv_bfloat16* __restrict__ hi,
                                  __nv_bfloat16* __restrict__ lo) {
    int g = blockIdx.x * blockDim.x + threadIdx.x;
    if (g >= R3r) return;
    int n = g % 768;
    int t = g / 768;
    int b4 = t / 64, hw = t % 64;
    float v[8];
#pragma unroll
    for (int c = 0; c < 8; c++)
        v[c] = x[(size_t)((b4 * 8 + c) * 64 + hw) * 768 + n];
    long r = (long)n * BATCH + t;
    *(float4*)(out + r * 32)     = make_float4(v[0], v[1], v[2], v[3]);
    *(float4*)(out + r * 32 + 4) = make_float4(v[4], v[5], v[6], v[7]);
    __nv_bfloat16 h[8], l[8];
#pragma unroll
    for (int c = 0; c < 8; c++) {
        h[c] = __float2bfloat16(v[c]);
        l[c] = __float2bfloat16(v[c] - __bfloat162float(h[c]));
    }
    *(uint4*)(hi + r * 32) = *(uint4*)h;
    *(uint4*)(lo + r * 32) = *(uint4*)l;
}

__global__ void permute_out_kernel(const float* __restrict__ y, float* __restrict__ out) {
    int idx = blockIdx.x * blockDim.x + threadIdx.x;
    if (idx >= R3r) return;
    int n = idx % 768;
    int t = idx / 768;
    out[idx] = y[n * BATCH + t];
}

__global__ void pool_kernel(const float* __restrict__ in, float* __restrict__ out,
                            int out_nodes, int F, int G,
                            __nv_bfloat16* __restrict__ hi,
                            __nv_bfloat16* __restrict__ lo) {
    int idx = blockIdx.x * blockDim.x + threadIdx.x;
    int total = out_nodes * BATCH * F;
    if (idx >= total) return;
    int f  = idx % F;
    int rb = idx / F;
    long src    = ((long)((rb / BATCH) * 4) * BATCH + (rb % BATCH)) * F + f;
    long stride = (long)BATCH * F;
    float m = in[src];
    m = fmaxf(m, in[src + stride]);
    m = fmaxf(m, in[src + 2 * stride]);
    m = fmaxf(m, in[src + 3 * stride]);
    long a = (long)rb * G + f;
    out[a] = m;
    __nv_bfloat16 h = __float2bfloat16(m);
    hi[a] = h;
    lo[a] = __float2bfloat16(m - __bfloat162float(h));
}

__global__ void unpool_concat_split_kernel(const float* __restrict__ a,
                                           const float* __restrict__ skip,
                                           __nv_bfloat16* __restrict__ hi,
                                           __nv_bfloat16* __restrict__ lo,
                                           int out_nodes, int Fa, int Fb) {
    int F = Fa + Fb;
    long total = (long)out_nodes * BATCH * F;
    long idx = (long)blockIdx.x * blockDim.x + threadIdx.x;
    if (idx >= total) return;
    int f = (int)(idx % F);
    long r = idx / F;
    int b = (int)(r % BATCH);
    int n = (int)(r / BATCH);
    float v;
    if (f < Fa) v = a[((long)(n / 4) * BATCH + b) * Fa + f];
    else        v = skip[r * Fb + (f - Fa)];
    __nv_bfloat16 h = __float2bfloat16(v);
    hi[idx] = h;
    lo[idx] = __float2bfloat16(v - __bfloat162float(h));
}

// Pack B' (N x 3K) bf16 from fp32 W (K x N): segments [Bhi | Blo | Bhi]
__global__ void pack_b_kernel(const float* __restrict__ W, __nv_bfloat16* __restrict__ Bp,
                              int K, int N, int K3) {
    int idx = blockIdx.x * blockDim.x + threadIdx.x;
    int total = N * K3;
    if (idx >= total) return;
    int q = idx % K3;
    int n = idx / K3;
    int seg = (q >= 2 * K) ? 2 : ((q >= K) ? 1 : 0);
    int k = q - seg * K;
    float w = W[(long)k * N + n];
    __nv_bfloat16 h = __float2bfloat16(w);
    Bp[idx] = (seg == 1) ? __float2bfloat16(w - __bfloat162float(h)) : h;
}

// Clenshaw-pack decoder weights: V (Fin x 4Fout), V0=W0-W2, V1=W1-W3, V2=W2, V3=W3
__global__ void pack_w_kernel(const float* __restrict__ w, float* __restrict__ V,
                              int Fin, int Fout) {
    int idx = blockIdx.x * blockDim.x + threadIdx.x;
    int total = Fin * 4 * Fout;
    if (idx >= total) return;
    int o = idx % Fout;
    int rest = idx / Fout;
    int p = rest % 4;
    int f = rest / 4;
    float v = w[((long)p * Fin + f) * Fout + o];
    if (p == 0) v -= w[((long)2 * Fin + f) * Fout + o];
    if (p == 1) v -= w[((long)3 * Fin + f) * Fout + o];
    V[idx] = v;
}

// ---- BatchNorm in fp32 ----
__global__ void bn_stats_kernel(const float* __restrict__ x, int rows, int F, int ld,
                                int chunks, float* __restrict__ stats) {
    int g = blockIdx.x * blockDim.x + threadIdx.x;
    int total = F * chunks;
    if (g >= total) return;
    int f = g % F;
    int c = g / F;
    float s = 0.f, q = 0.f;
    for (int r = c; r < rows; r += chunks) {
        float v = x[(long)r * ld + f];
        s += v;
        q = fmaf(v, v, q);
    }
    atomicAdd(&stats[f], s);
    atomicAdd(&stats[256 + f], q);
}

// BN apply + ReLU with finalize folded in (per-block smem recompute of
// scale/shift from the accumulated stats); optional bf16 hi/lo emission.
__global__ void bn_apply_kernel(float* __restrict__ x, long total, int F, int ld,
                                const float* __restrict__ stats, float inv_rows,
                                const float* __restrict__ gamma,
                                const float* __restrict__ beta,
                                __nv_bfloat16* __restrict__ hi,
                                __nv_bfloat16* __restrict__ lo) {
    __shared__ float ssc[512];
    if (threadIdx.x < F) {
        int f = threadIdx.x;
        float mu  = stats[f] * inv_rows;
        float var = stats[256 + f] * inv_rows - mu * mu;
        float scale = gamma[f] * rsqrtf(var + 1e-5f);
        ssc[f] = scale;
        ssc[256 + f] = beta[f] - mu * scale;
    }
    __syncthreads();
    long idx = (long)blockIdx.x * blockDim.x + threadIdx.x;
    if (idx >= total) return;
    int f = (int)(idx % F);
    long r = idx / F;
    long a = r * ld + f;
    float v = fmaf(x[a], ssc[f], ssc[256 + f]);
    v = v > 0.f ? v : 0.f;
    x[a] = v;
    if (hi) {
        __nv_bfloat16 h = __float2bfloat16(v);
        hi[a] = h;
        lo[a] = __float2bfloat16(v - __bfloat162float(h));
    }
}

__global__ void gemv4_kernel(const float* __restrict__ X, const float* __restrict__ w,
                             int rows, float* __restrict__ u0, float* __restrict__ u1,
                             float* __restrict__ u2, float* __restrict__ u3) {
    __shared__ float ws[128];
    if (threadIdx.x < 128) ws[threadIdx.x] = w[threadIdx.x];
    __syncthreads();
    int r = blockIdx.x * blockDim.x + threadIdx.x;
    if (r >= rows) return;
    const float* xr = X + (long)r * 32;
    float s0 = 0, s1 = 0, s2 = 0, s3 = 0;
#pragma unroll
    for (int f = 0; f < 32; f++) {
        float v = xr[f];
        s0 += v * ws[f];
        s1 += v * ws[32 + f];
        s2 += v * ws[64 + f];
        s3 += v * ws[96 + f];
    }
    u0[r] = s0 - s2; u1[r] = s1 - s3; u2[r] = s2; u3[r] = s3;
}

// ---------------------------------------------------------------------------
// Host-side helpers
// ---------------------------------------------------------------------------
static void run_tc(int M, int N, int K,
                   const __nv_bfloat16* Ahi, const __nv_bfloat16* Alo,
                   const __nv_bfloat16* Bp, float* C, int ldc,
                   int split = 0, float* o0 = nullptr, float* o1 = nullptr,
                   float* o2 = nullptr, float* o3 = nullptr) {
    int K3 = 3 * K;
    if (N % 128 == 0) {
        int sm = 2048 + 2 * (16384 + 16384);
        cudaFuncSetAttribute(tc_gemm<128>, cudaFuncAttributeMaxDynamicSharedMemorySize, sm);
        tc_gemm<128><<<dim3(N / 128, M / 128), 128, sm>>>(M, N, K, K3, Ahi, Alo, Bp,
                                                          C, ldc, split, o0, o1, o2, o3);
    } else if (N == 64) {
        int sm = 2048 + 2 * (16384 + 8192);
        cudaFuncSetAttribute(tc_gemm<64>, cudaFuncAttributeMaxDynamicSharedMemorySize, sm);
        tc_gemm<64><<<dim3(1, M / 128), 128, sm>>>(M, N, K, K3, Ahi, Alo, Bp,
                                                   C, ldc, split, o0, o1, o2, o3);
    } else {
        int sm = 2048 + 2 * (16384 + 4096);
        cudaFuncSetAttribute(tc_gemm<32>, cudaFuncAttributeMaxDynamicSharedMemorySize, sm);
        tc_gemm<32><<<dim3(1, M / 128), 128, sm>>>(M, N, K, K3, Ahi, Alo, Bp,
                                                   C, ldc, split, o0, o1, o2, o3);
    }
}

static void run_bn(float* xbuf, int rows, int F, int ld, const float* gamma,
                   const float* beta, float* statsRegion,
                   __nv_bfloat16* hi = nullptr, __nv_bfloat16* lo = nullptr) {
    const int chunks = 256;
    bn_stats_kernel<<<cdiv(F * chunks, 256), 256>>>(xbuf, rows, F, ld, chunks, statsRegion);
    long n = (long)rows * F;
    bn_apply_kernel<<<cdiv(n, 256), 256>>>(xbuf, n, F, ld, statsRegion,
                                           1.0f / (float)rows, gamma, beta, hi, lo);
}

static void cheb_fill(const Csr& cs, int nodes, int Fin, float* X,
                      __nv_bfloat16* hi, __nv_bfloat16* lo) {
    int W = BATCH * Fin, G = 4 * Fin, RS = BATCH * 4 * Fin;
    long Kb = 4 * Fin;
    run_spmm(cs, nodes, W, Fin, G, RS, 1.f, X, 0.f, nullptr, X + Fin, nullptr,
             hi + Fin, lo + Fin, Kb);
    run_spmm(cs, nodes, W, Fin, G, RS, 2.f, X + Fin, -1.f, X, X + 2 * Fin, nullptr,
             hi + 2 * Fin, lo + 2 * Fin, Kb);
    run_spmm(cs, nodes, W, Fin, G, RS, 2.f, X + 2 * Fin, -1.f, X + Fin, X + 3 * Fin, nullptr,
             hi + 3 * Fin, lo + 3 * Fin, Kb);
}

static void clenshaw_tail(const Csr& cs, int nodes, int F,
                          float* u0, float* u1, float* u2, float* u3) {
    int W = BATCH * F, RS = BATCH * F;
    run_spmm(cs, nodes, W, F, F, RS, 2.f, u3, 1.f, u2, u2, u0);
    run_spmm(cs, nodes, W, F, F, RS, 2.f, u2, 1.f, u1, u1, nullptr);
    run_spmm(cs, nodes, W, F, F, RS, 1.f, u1, 1.f, u0, u0, nullptr);
}

// ---------------------------------------------------------------------------
extern "C" void kernel_launch(void* const* d_in, const int* in_sizes, int n_in,
                              void* d_out, int out_size) {
    const float* x    = (const float*)d_in[0];
    const float* L3   = (const float*)d_in[1];
    const float* L2   = (const float*)d_in[2];
    const float* L1   = (const float*)d_in[3];
    const float* L0   = (const float*)d_in[4];
    const float* w_e3a = (const float*)d_in[5];
    const float* g_e3a = (const float*)d_in[6];
    const float* b_e3a = (const float*)d_in[7];
    const float* w_e3b = (const float*)d_in[8];
    const float* g_e3b = (const float*)d_in[9];
    const float* b_e3b = (const float*)d_in[10];
    const float* w_e2  = (const float*)d_in[11];
    const float* g_e2  = (const float*)d_in[12];
    const float* b_e2  = (const float*)d_in[13];
    const float* w_e1  = (const float*)d_in[14];
    const float* g_e1  = (const float*)d_in[15];
    const float* b_e1  = (const float*)d_in[16];
    const float* w_e0  = (const float*)d_in[17];
    const float* g_e0  = (const float*)d_in[18];
    const float* b_e0  = (const float*)d_in[19];
    const float* w_d1  = (const float*)d_in[20];
    const float* g_d1  = (const float*)d_in[21];
    const float* b_d1  = (const float*)d_in[22];
    const float* w_d2  = (const float*)d_in[23];
    const float* g_d2  = (const float*)d_in[24];
    const float* b_d2  = (const float*)d_in[25];
    const float* w_d3  = (const float*)d_in[26];
    const float* g_d3  = (const float*)d_in[27];
    const float* b_d3  = (const float*)d_in[28];
    const float* w_out = (const float*)d_in[29];

    float* pool = nullptr; float* stats = nullptr;
    int* ccols = nullptr; float* cvals = nullptr; int* cnnz = nullptr;
    __nv_bfloat16 *Ahi = nullptr, *Alo = nullptr, *Bp = nullptr;
    cudaGetSymbolAddress((void**)&pool, g_pool);
    cudaGetSymbolAddress((void**)&stats, g_stats);
    cudaGetSymbolAddress((void**)&ccols, g_ccols);
    cudaGetSymbolAddress((void**)&cvals, g_cvals);
    cudaGetSymbolAddress((void**)&cnnz, g_cnnz);
    cudaGetSymbolAddress((void**)&Ahi, g_ahi);
    cudaGetSymbolAddress((void**)&Alo, g_alo);
    cudaGetSymbolAddress((void**)&Bp, g_bp);

    float* S3 = pool + OFF_S3;
    float* S2 = pool + OFF_S2;
    float* S1 = pool + OFF_S1;
    float* XA = pool + OFF_XA;
    float* XB = pool + OFF_XB;
    float* X2 = pool + OFF_X2;
    float* X1 = pool + OFF_X1;
    float* X0 = pool + OFF_X0;
    float* T0 = pool + OFF_T0;
    float* T1 = pool + OFF_T1;
    float* T2 = pool + OFF_T2;
    float* T3 = pool + OFF_T3;
    float* U  = pool + OFF_U;
    float* Vw = pool + OFF_W;

    Csr cs3 = { ccols,                cvals,                cnnz,                N3 };
    Csr cs2 = { ccols + C3,           cvals + C3,           cnnz + N3,           N2 };
    Csr cs1 = { ccols + C3 + C2,      cvals + C3 + C2,      cnnz + N3 + N2,      N1 };
    Csr cs0 = { ccols + C3 + C2 + C1, cvals + C3 + C2 + C1, cnnz + N3 + N2 + N1, N0 };

    cudaMemsetAsync(stats, 0, 4096 * sizeof(float));

    build_csr_kernel<<<cdiv(N3, 8), 256>>>(L3, N3, (int*)cs3.cols, (float*)cs3.vals, (int*)cs3.nnz);
    build_csr_kernel<<<cdiv(N2, 8), 256>>>(L2, N2, (int*)cs2.cols, (float*)cs2.vals, (int*)cs2.nnz);
    build_csr_kernel<<<cdiv(N1, 8), 256>>>(L1, N1, (int*)cs1.cols, (float*)cs1.vals, (int*)cs1.nnz);
    build_csr_kernel<<<cdiv(N0, 8), 256>>>(L0, N0, (int*)cs0.cols, (float*)cs0.vals, (int*)cs0.nnz);

    // ---- input permute -> XA block0 (G=32) + bf16 (K=32) ----
    permute_in_kernel<<<cdiv(R3r, 256), 256>>>(x, XA, Ahi, Alo);

    // ---- e3a ----
    cheb_fill(cs3, N3, 8, XA, Ahi, Alo);
    pack_b_kernel<<<cdiv(32 * 96, 256), 256>>>(w_e3a, Bp, 32, 32, 96);
    run_tc(R3r, 32, 32, Ahi, Alo, Bp, XB, 128);
    run_bn(XB, R3r, 32, 128, g_e3a, b_e3a, stats, Ahi, Alo);

    // ---- e3b ----
    cheb_fill(cs3, N3, 32, XB, Ahi, Alo);
    pack_b_kernel<<<cdiv(64 * 384, 256), 256>>>(w_e3b, Bp, 128, 64, 384);
    run_tc(R3r, 64, 128, Ahi, Alo, Bp, S3, 64);
    run_bn(S3, R3r, 64, 64, g_e3b, b_e3b, stats + 512);

    // ---- e2 ----
    pool_kernel<<<cdiv((long)R2r * 64, 256), 256>>>(S3, X2, N2, 64, 256, Ahi, Alo);
    cheb_fill(cs2, N2, 64, X2, Ahi, Alo);
    pack_b_kernel<<<cdiv(128 * 768, 256), 256>>>(w_e2, Bp, 256, 128, 768);
    run_tc(R2r, 128, 256, Ahi, Alo, Bp, S2, 128);
    run_bn(S2, R2r, 128, 128, g_e2, b_e2, stats + 1024);

    // ---- e1 ----
    pool_kernel<<<cdiv((long)R1r * 128, 256), 256>>>(S2, X1, N1, 128, 512, Ahi, Alo);
    cheb_fill(cs1, N1, 128, X1, Ahi, Alo);
    pack_b_kernel<<<cdiv(256 * 1536, 256), 256>>>(w_e1, Bp, 512, 256, 1536);
    run_tc(R1r, 256, 512, Ahi, Alo, Bp, S1, 256);
    run_bn(S1, R1r, 256, 256, g_e1, b_e1, stats + 1536);

    // ---- e0 ----
    pool_kernel<<<cdiv((long)R0r * 256, 256), 256>>>(S1, X0, N0, 256, 1024, Ahi, Alo);
    cheb_fill(cs0, N0, 256, X0, Ahi, Alo);
    pack_b_kernel<<<cdiv(256 * 3072, 256), 256>>>(w_e0, Bp, 1024, 256, 3072);
    run_tc(R0r, 256, 1024, Ahi, Alo, Bp, T0, 256);
    run_bn(T0, R0r, 256, 256, g_e0, b_e0, stats + 2048);

    // ---- d1 ----
    unpool_concat_split_kernel<<<cdiv((long)R1r * 512, 256), 256>>>(T0, S1, Ahi, Alo, N1, 256, 256);
    pack_w_kernel<<<cdiv(512 * 512, 256), 256>>>(w_d1, Vw, 512, 128);
    pack_b_kernel<<<cdiv(512 * 1536, 256), 256>>>(Vw, Bp, 512, 512, 1536);
    run_tc(R1r, 512, 512, Ahi, Alo, Bp, nullptr, 0, 128, T0, T1, T2, T3);
    clenshaw_tail(cs1, N1, 128, T0, T1, T2, T3);
    run_bn(T0, R1r, 128, 128, g_d1, b_d1, stats + 2560);

    // ---- d2 ----
    unpool_concat_split_kernel<<<cdiv((long)R2r * 256, 256), 256>>>(T0, S2, Ahi, Alo, N2, 128, 128);
    pack_w_kernel<<<cdiv(256 * 256, 256), 256>>>(w_d2, Vw, 256, 64);
    pack_b_kernel<<<cdiv(256 * 768, 256), 256>>>(Vw, Bp, 256, 256, 768);
    run_tc(R2r, 256, 256, Ahi, Alo, Bp, nullptr, 0, 64, T0, T1, T2, T3);
    clenshaw_tail(cs2, N2, 64, T0, T1, T2, T3);
    run_bn(T0, R2r, 64, 64, g_d2, b_d2, stats + 3072);

    // ---- d3 ----
    unpool_concat_split_kernel<<<cdiv((long)R3r * 128, 256), 256>>>(T0, S3, Ahi, Alo, N3, 64, 64);
    pack_w_kernel<<<cdiv(128 * 128, 256), 256>>>(w_d3, Vw, 128, 32);
    pack_b_kernel<<<cdiv(128 * 384, 256), 256>>>(Vw, Bp, 128, 128, 384);
    run_tc(R3r, 128, 128, Ahi, Alo, Bp, nullptr, 0, 32, T0, T1, T2, T3);
    clenshaw_tail(cs3, N3, 32, T0, T1, T2, T3);
    run_bn(T0, R3r, 32, 32, g_d3, b_d3, stats + 3584);

    // ---- output conv (Fout=1) ----
    float* u0 = U;
    float* u1 = U + R3r;
    float* u2 = U + 2 * (long)R3r;
    float* u3 = U + 3 * (long)R3r;
    gemv4_kernel<<<cdiv(R3r, 256), 256>>>(T0, w_out, R3r, u0, u1, u2, u3);
    run_spmm(cs3, N3, 256, 256, 256, 256, 2.f, u3, 1.f, u2, u2, u0);
    run_spmm(cs3, N3, 256, 256, 256, 256, 2.f, u2, 1.f, u1, u1, nullptr);
    run_spmm(cs3, N3, 256, 256, 256, 256, 1.f, u1, 1.f, u0, u0, nullptr);

    permute_out_kernel<<<cdiv(R3r, 256), 256>>>(u0, (float*)d_out);
}

// round 14
// speedup vs baseline: 1.3664x; 1.3664x over previous
#include <cuda_runtime.h>
#include <cuda_bf16.h>
#include <cstdint>

// ---------------------------------------------------------------------------
// SphereVoxelConv: DeepSphere U-Net forward.
// Round 14: byte-identical resubmission of the round-10 artifact (best
// measured: 1528us) as a reproducibility / noise-floor measurement after
// three rounds of micro-changes that regressed inexplicably (R13: +559us
// from a ~5us-cost change => suspected DVFS run-to-run variance).
// fp32 BN, fused bf16-split emission, tcgen05 bf16 2-term split GEMMs,
// CSR SpMM L-applies, Clenshaw decoder.
// ---------------------------------------------------------------------------

#if defined(__CUDA_ARCH_FEAT_SM103_ALL) || defined(__CUDA_ARCH_FEAT_SM100_ALL) || defined(__CUDA_ARCH_FEAT_SM101_ALL)
#define HAS_TCGEN05 1
#else
#define HAS_TCGEN05 0
#endif

#define BATCH 256            // B*H*W = 4*8*8
constexpr int N3 = 768, N2 = 192, N1 = 48, N0 = 12;
constexpr int R3r = N3 * BATCH;   // 196608
constexpr int R2r = N2 * BATCH;   // 49152
constexpr int R1r = N1 * BATCH;   // 12288
constexpr int R0r = N0 * BATCH;   // 3072

// ---- static fp32 scratch pool ----
constexpr size_t SZ_S3 = (size_t)R3r * 64;
constexpr size_t SZ_S2 = (size_t)R2r * 128;
constexpr size_t SZ_S1 = (size_t)R1r * 256;
constexpr size_t SZ_XA = (size_t)R3r * 32;
constexpr size_t SZ_XB = (size_t)R3r * 128;
constexpr size_t SZ_X2 = (size_t)R2r * 256;
constexpr size_t SZ_X1 = (size_t)R1r * 512;
constexpr size_t SZ_X0 = (size_t)R0r * 1024;
constexpr size_t SZ_T  = (size_t)R3r * 32;
constexpr size_t SZ_U  = (size_t)R3r * 4;
constexpr size_t SZ_W  = 512 * 512;

constexpr size_t OFF_S3 = 0;
constexpr size_t OFF_S2 = OFF_S3 + SZ_S3;
constexpr size_t OFF_S1 = OFF_S2 + SZ_S2;
constexpr size_t OFF_XA = OFF_S1 + SZ_S1;
constexpr size_t OFF_XB = OFF_XA + SZ_XA;
constexpr size_t OFF_X2 = OFF_XB + SZ_XB;
constexpr size_t OFF_X1 = OFF_X2 + SZ_X2;
constexpr size_t OFF_X0 = OFF_X1 + SZ_X1;
constexpr size_t OFF_T0 = OFF_X0 + SZ_X0;
constexpr size_t OFF_T1 = OFF_T0 + SZ_T;
constexpr size_t OFF_T2 = OFF_T1 + SZ_T;
constexpr size_t OFF_T3 = OFF_T2 + SZ_T;
constexpr size_t OFF_U  = OFF_T3 + SZ_T;
constexpr size_t OFF_W  = OFF_U + SZ_U;
constexpr size_t POOL_TOTAL = OFF_W + SZ_W;

__device__ __align__(256) float g_pool[POOL_TOTAL];
__device__ float g_stats[4096];   // 8 regions of 512 (sum / sumsq)
__device__ float g_bnsc[4096];    // 8 regions of 512 (scale / shift)

constexpr size_t BF_MAX = (size_t)R3r * 128;
__device__ __align__(256) __nv_bfloat16 g_ahi[BF_MAX];
__device__ __align__(256) __nv_bfloat16 g_alo[BF_MAX];
__device__ __align__(256) __nv_bfloat16 g_bp[1 << 20];

constexpr int C3 = N3 * N3, C2 = N2 * N2, C1 = N1 * N1, C0 = N0 * N0;
__device__ int   g_ccols[C3 + C2 + C1 + C0];
__device__ float g_cvals[C3 + C2 + C1 + C0];
__device__ int   g_cnnz[N3 + N2 + N1 + N0];

static inline int cdiv(long a, long b) { return (int)((a + b - 1) / b); }

// ---------------------------------------------------------------------------
// PTX helpers
// ---------------------------------------------------------------------------
__device__ __forceinline__ uint32_t smem_u32(const void* p) {
    uint32_t a;
    asm("{ .reg .u64 t; cvta.to.shared.u64 t, %1; cvt.u32.u64 %0, t; }"
        : "=r"(a) : "l"(p));
    return a;
}

#if HAS_TCGEN05
__device__ __forceinline__ uint32_t elect1() {
    uint32_t p;
    asm volatile("{ .reg .pred p; elect.sync _|p, 0xFFFFFFFF; selp.b32 %0,1,0,p; }"
                 : "=r"(p));
    return p;
}

__device__ __forceinline__ void mb_init(uint32_t addr, uint32_t cnt) {
    asm volatile("mbarrier.init.shared.b64 [%0], %1;" :: "r"(addr), "r"(cnt) : "memory");
}

__device__ __forceinline__ void mb_wait(uint32_t addr, uint32_t par) {
    asm volatile(
        "{\n\t"
        ".reg .pred P1;\n\t"
        "WAIT_%=:\n\t"
        "mbarrier.try_wait.parity.acquire.cta.shared::cta.b64 P1, [%0], %1, 0x989680;\n\t"
        "@P1 bra.uni DONE_%=;\n\t"
        "bra.uni WAIT_%=;\n\t"
        "DONE_%=:\n\t"
        "}"
        :: "r"(addr), "r"(par) : "memory");
}

__device__ __forceinline__ void tc_ld16(uint32_t* r, uint32_t ta) {
    asm volatile(
        "tcgen05.ld.sync.aligned.32x32b.x16.b32 "
        "{%0,%1,%2,%3,%4,%5,%6,%7,%8,%9,%10,%11,%12,%13,%14,%15}, [%16];"
        : "=r"(r[0]), "=r"(r[1]), "=r"(r[2]), "=r"(r[3]),
          "=r"(r[4]), "=r"(r[5]), "=r"(r[6]), "=r"(r[7]),
          "=r"(r[8]), "=r"(r[9]), "=r"(r[10]), "=r"(r[11]),
          "=r"(r[12]), "=r"(r[13]), "=r"(r[14]), "=r"(r[15])
        : "r"(ta));
}
#endif  // HAS_TCGEN05

constexpr uint64_t DESC_BASE =
    (uint64_t(2) << 61) | (uint64_t(1) << 46) | (uint64_t(64) << 32) | (uint64_t(1) << 16);

// ---------------------------------------------------------------------------
// Tile loaders (SW128): A segments along K' are [Ahi | Ahi | Alo]
// ---------------------------------------------------------------------------
__device__ __forceinline__ void load_tile_A(char* smem, int off,
    const __nv_bfloat16* __restrict__ Ahi, const __nv_bfloat16* __restrict__ Alo,
    int rowBase, int K, int K3, int twoK, int q0, int tid) {
#pragma unroll
    for (int i = 0; i < 8; i++) {
        int g = tid + i * 128;
        int r = g >> 3, c = (g & 7) * 8;
        int kq = q0 + c;
        uint4 v = make_uint4(0u, 0u, 0u, 0u);
        if (kq < K3) {
            const __nv_bfloat16* src = (kq >= twoK) ? Alo : Ahi;
            int k = kq;
            if (k >= twoK) k -= twoK; else if (k >= K) k -= K;
            v = *(const uint4*)(src + (size_t)(rowBase + r) * K + k);
        }
        uint32_t bo = (uint32_t)(r * 128 + c * 2);
        *(uint4*)(smem + off + (bo ^ ((bo >> 3) & 0x70))) = v;
    }
}

template<int BN>
__device__ __forceinline__ void load_tile_B(char* smem, int off,
    const __nv_bfloat16* __restrict__ Bp,
    int colBase, int K3, int q0, int tid) {
    constexpr int BG = BN * 8 / 128;
#pragma unroll
    for (int i = 0; i < BG; i++) {
        int g = tid + i * 128;
        int r = g >> 3, c = (g & 7) * 8;
        int kq = q0 + c;
        uint4 v = make_uint4(0u, 0u, 0u, 0u);
        if (kq < K3)
            v = *(const uint4*)(Bp + (size_t)(colBase + r) * K3 + kq);
        uint32_t bo = (uint32_t)(r * 128 + c * 2);
        *(uint4*)(smem + off + (bo ^ ((bo >> 3) & 0x70))) = v;
    }
}

// ---------------------------------------------------------------------------
// GEMM: C(MxN) = splitA(MxK) * Bp(Nx3K), fp32 out.
// ---------------------------------------------------------------------------
template<int BN>
__global__ __launch_bounds__(128)
void tc_gemm(int M, int Ntot, int K, int K3,
             const __nv_bfloat16* __restrict__ Ahi,
             const __nv_bfloat16* __restrict__ Alo,
             const __nv_bfloat16* __restrict__ Bp,
             float* __restrict__ C, int ldc,
             int split, float* __restrict__ o0, float* __restrict__ o1,
             float* __restrict__ o2, float* __restrict__ o3)
{
#if HAS_TCGEN05
    extern __shared__ char smem[];
    const int tid = threadIdx.x;
    const int wid = tid >> 5;
    const int lane = tid & 31;
    const int rowBase = blockIdx.y * 128;
    const int colBase = blockIdx.x * BN;

    const uint32_t sbase = smem_u32(smem);
    const uint32_t hdr = sbase;                  // [0] tmem ptr, [8],[16] mbarriers
    const uint32_t tbase = (sbase + 1024 + 1023) & ~1023u;
    const int tchar = (int)(tbase - sbase);
    constexpr int ABYTES = 128 * 128;
    constexpr int BBYTES = BN * 128;
    const int offA0 = tchar;
    const int offB0 = tchar + ABYTES;
    const int offA1 = tchar + ABYTES + BBYTES;
    const int offB1 = tchar + 2 * ABYTES + BBYTES;
    constexpr uint32_t TCOLS = (BN < 32) ? 32u : (uint32_t)BN;

    if (tid == 0) { mb_init(hdr + 8, 1); mb_init(hdr + 16, 1); }
    if (wid == 0) {
        asm volatile("tcgen05.alloc.cta_group::1.sync.aligned.shared::cta.b32 [%0], %1;"
                     :: "r"(hdr), "r"(TCOLS) : "memory");
        asm volatile("tcgen05.relinquish_alloc_permit.cta_group::1.sync.aligned;");
    }
    __syncthreads();
    uint32_t tmem;
    asm volatile("ld.shared.b32 %0, [%1];" : "=r"(tmem) : "r"(hdr));

    const uint32_t idesc = 0x490u | ((uint32_t)(BN / 8) << 17) | (8u << 24);
    const int nch = (K3 + 63) >> 6;
    const int twoK = 2 * K;

    load_tile_A(smem, offA0, Ahi, Alo, rowBase, K, K3, twoK, 0, tid);
    load_tile_B<BN>(smem, offB0, Bp, colBase, K3, 0, tid);
    asm volatile("fence.proxy.async.shared::cta;" ::: "memory");
    __syncthreads();

    int ph0 = 0, ph1 = 0;
    for (int ch = 0; ch < nch; ch++) {
        const int buf = ch & 1;
        const int offA = buf ? offA1 : offA0;
        const int offB = buf ? offB1 : offB0;
        if (wid == 0 && elect1()) {
            uint64_t da = DESC_BASE | (uint64_t)(((sbase + offA) >> 4) & 0x3FFF);
            uint64_t db = DESC_BASE | (uint64_t)(((sbase + offB) >> 4) & 0x3FFF);
#pragma unroll
            for (int s = 0; s < 4; s++) {
                uint32_t en = (ch > 0 || s > 0) ? 1u : 0u;
                asm volatile(
                    "{\n\t.reg .pred p;\n\tsetp.ne.u32 p, %5, 0;\n\t"
                    "tcgen05.mma.cta_group::1.kind::f16 [%0], %1, %2, %3, {%4, %4, %4, %4}, p;\n\t}"
                    :: "r"(tmem), "l"(da + s * 2), "l"(db + s * 2), "r"(idesc),
                       "r"(0u), "r"(en) : "memory");
            }
            asm volatile(
                "tcgen05.commit.cta_group::1.mbarrier::arrive::one.shared::cluster.b64 [%0];"
                :: "r"(hdr + 8 + 8 * buf) : "memory");
        }
        if (ch + 1 < nch) {
            if (ch >= 1) {
                if (((ch + 1) & 1) == 0) { mb_wait(hdr + 8, ph0); ph0 ^= 1; }
                else                     { mb_wait(hdr + 16, ph1); ph1 ^= 1; }
            }
            const int offAn = buf ? offA0 : offA1;
            const int offBn = buf ? offB0 : offB1;
            load_tile_A(smem, offAn, Ahi, Alo, rowBase, K, K3, twoK, (ch + 1) * 64, tid);
            load_tile_B<BN>(smem, offBn, Bp, colBase, K3, (ch + 1) * 64, tid);
            asm volatile("fence.proxy.async.shared::cta;" ::: "memory");
        }
        __syncthreads();
    }
    if (((nch - 1) & 1) == 0) mb_wait(hdr + 8, ph0);
    else                      mb_wait(hdr + 16, ph1);
    asm volatile("tcgen05.fence::after_thread_sync;" ::: "memory");

    // ---- epilogue ----
    const int gr = rowBase + wid * 32 + lane;
#pragma unroll 1
    for (int b0 = 0; b0 < BN; b0 += 32) {
        uint32_t r[32];
        tc_ld16(r, tmem + b0);
        tc_ld16(r + 16, tmem + b0 + 16);
        asm volatile("tcgen05.wait::ld.sync.aligned;" ::: "memory");
        if (split > 0) {
#pragma unroll
            for (int c = 0; c < 32; c += 4) {
                int gc = colBase + b0 + c;
                int p = gc / split, lc = gc - p * split;
                float* op = (p == 0) ? o0 : (p == 1) ? o1 : (p == 2) ? o2 : o3;
                float4 v = make_float4(__uint_as_float(r[c]), __uint_as_float(r[c + 1]),
                                       __uint_as_float(r[c + 2]), __uint_as_float(r[c + 3]));
                *(float4*)(op + (size_t)gr * split + lc) = v;
            }
        } else {
#pragma unroll
            for (int c = 0; c < 32; c += 4) {
                float4 v = make_float4(__uint_as_float(r[c]), __uint_as_float(r[c + 1]),
                                       __uint_as_float(r[c + 2]), __uint_as_float(r[c + 3]));
                *(float4*)(C + (size_t)gr * ldc + colBase + b0 + c) = v;
            }
        }
    }
    __syncthreads();
    if (wid == 0)
        asm volatile("tcgen05.dealloc.cta_group::1.sync.aligned.b32 %0, %1;"
                     :: "r"(tmem), "r"(TCOLS));
#else
    // -------- SIMT fallback (generic PTX pass; correct, slow) --------
    const int tid = threadIdx.x;
    const int rowBase = blockIdx.y * 128;
    const int colBase = blockIdx.x * BN;
    const int gr = rowBase + tid;
    const __nv_bfloat16* ah = Ahi + (size_t)gr * K;
    const __nv_bfloat16* al = Alo + (size_t)gr * K;
    for (int j0 = 0; j0 < BN; j0 += 8) {
        float acc[8];
#pragma unroll
        for (int j = 0; j < 8; j++) acc[j] = 0.f;
        for (int k = 0; k < K; k++) {
            float av = __bfloat162float(ah[k]);
            float lv = __bfloat162float(al[k]);
#pragma unroll
            for (int j = 0; j < 8; j++) {
                const __nv_bfloat16* b = Bp + (size_t)(colBase + j0 + j) * K3;
                float bh = __bfloat162float(b[k]);
                float bl = __bfloat162float(b[K + k]);
                acc[j] += av * bh + av * bl + lv * bh;
            }
        }
#pragma unroll
        for (int j = 0; j < 8; j++) {
            int gc = colBase + j0 + j;
            if (split > 0) {
                int p = gc / split, lc = gc - p * split;
                float* op = (p == 0) ? o0 : (p == 1) ? o1 : (p == 2) ? o2 : o3;
                op[(size_t)gr * split + lc] = acc[j];
            } else {
                C[(size_t)gr * ldc + gc] = acc[j];
            }
        }
    }
#endif
}

// ---------------------------------------------------------------------------
// CSR build (deterministic ballot-scan, 1 warp per row)
// ---------------------------------------------------------------------------
__global__ void build_csr_kernel(const float* __restrict__ L, int n,
                                 int* __restrict__ cols, float* __restrict__ vals,
                                 int* __restrict__ nnz) {
    int row = blockIdx.x * 8 + (threadIdx.x >> 5);
    if (row >= n) return;
    int lane = threadIdx.x & 31;
    unsigned lt = (1u << lane) - 1u;
    int cnt = 0;
    for (int c0 = 0; c0 < n; c0 += 32) {
        int c = c0 + lane;
        float v = (c < n) ? L[(long)row * n + c] : 0.f;
        unsigned m = __ballot_sync(0xffffffffu, v != 0.f);
        if (v != 0.f) {
            int pos = cnt + __popc(m & lt);
            cols[(long)row * n + pos] = c;
            vals[(long)row * n + pos] = v;
        }
        cnt += __popc(m);
    }
    if (lane == 0) nnz[row] = cnt;
}

// ---------------------------------------------------------------------------
// SpMM: out = alpha*(L in) + beta*cin, optional aux -= alpha*(L in),
// optional bf16 hi/lo emission of the final value (row stride Kb elements).
// ---------------------------------------------------------------------------
__global__ void spmm_kernel(int W4, int fshift, int fmask, int G4, long RS4,
                            float alpha, const float4* __restrict__ in,
                            float beta, const float4* __restrict__ cin,
                            float4* __restrict__ out, float4* __restrict__ aux,
                            __nv_bfloat16* __restrict__ hi,
                            __nv_bfloat16* __restrict__ lo, long Kb,
                            const int* __restrict__ cols,
                            const float* __restrict__ vals,
                            const int* __restrict__ nnz, int pitch) {
    __shared__ float sv[768];
    __shared__ int   sc[768];
    int node = blockIdx.y;
    int cnt = nnz[node];
    for (int j = threadIdx.x; j < cnt; j += blockDim.x) {
        sv[j] = vals[(long)node * pitch + j];
        sc[j] = cols[(long)node * pitch + j];
    }
    __syncthreads();
    int c4 = blockIdx.x * blockDim.x + threadIdx.x;
    if (c4 >= W4) return;
    int t  = c4 >> fshift;
    int f4 = c4 & fmask;
    long off = (long)t * G4 + f4;
    float4 acc = make_float4(0.f, 0.f, 0.f, 0.f);
    int j = 0;
    for (; j + 4 <= cnt; j += 4) {
        float v0 = sv[j], v1 = sv[j + 1], v2 = sv[j + 2], v3 = sv[j + 3];
        float4 x0 = in[(long)sc[j] * RS4 + off];
        float4 x1 = in[(long)sc[j + 1] * RS4 + off];
        float4 x2 = in[(long)sc[j + 2] * RS4 + off];
        float4 x3 = in[(long)sc[j + 3] * RS4 + off];
        acc.x = fmaf(v0, x0.x, acc.x); acc.y = fmaf(v0, x0.y, acc.y);
        acc.z = fmaf(v0, x0.z, acc.z); acc.w = fmaf(v0, x0.w, acc.w);
        acc.x = fmaf(v1, x1.x, acc.x); acc.y = fmaf(v1, x1.y, acc.y);
        acc.z = fmaf(v1, x1.z, acc.z); acc.w = fmaf(v1, x1.w, acc.w);
        acc.x = fmaf(v2, x2.x, acc.x); acc.y = fmaf(v2, x2.y, acc.y);
        acc.z = fmaf(v2, x2.z, acc.z); acc.w = fmaf(v2, x2.w, acc.w);
        acc.x = fmaf(v3, x3.x, acc.x); acc.y = fmaf(v3, x3.y, acc.y);
        acc.z = fmaf(v3, x3.z, acc.z); acc.w = fmaf(v3, x3.w, acc.w);
    }
    for (; j < cnt; j++) {
        float v0 = sv[j];
        float4 x0 = in[(long)sc[j] * RS4 + off];
        acc.x = fmaf(v0, x0.x, acc.x); acc.y = fmaf(v0, x0.y, acc.y);
        acc.z = fmaf(v0, x0.z, acc.z); acc.w = fmaf(v0, x0.w, acc.w);
    }
    acc.x *= alpha; acc.y *= alpha; acc.z *= alpha; acc.w *= alpha;
    long oidx = (long)node * RS4 + off;
    if (aux) {
        float4 a = aux[oidx];
        a.x -= acc.x; a.y -= acc.y; a.z -= acc.z; a.w -= acc.w;
        aux[oidx] = a;
    }
    if (beta != 0.f) {
        float4 ci = cin[oidx];
        acc.x = fmaf(beta, ci.x, acc.x); acc.y = fmaf(beta, ci.y, acc.y);
        acc.z = fmaf(beta, ci.z, acc.z); acc.w = fmaf(beta, ci.w, acc.w);
    }
    out[oidx] = acc;
    if (hi) {
        long e = ((long)node * BATCH + t) * Kb + 4 * f4;
        __nv_bfloat16 h[4], l[4];
        float vv[4] = { acc.x, acc.y, acc.z, acc.w };
#pragma unroll
        for (int q = 0; q < 4; q++) {
            h[q] = __float2bfloat16(vv[q]);
            l[q] = __float2bfloat16(vv[q] - __bfloat162float(h[q]));
        }
        *(uint2*)(hi + e) = *(uint2*)h;
        *(uint2*)(lo + e) = *(uint2*)l;
    }
}

struct Csr { const int* cols; const float* vals; const int* nnz; int pitch; };

static void run_spmm(const Csr& cs, int nodes, int W, int Fin, int G, int RS,
                     float alpha, const float* in, float beta, const float* cin,
                     float* out, float* aux,
                     __nv_bfloat16* hi = nullptr, __nv_bfloat16* lo = nullptr,
                     long Kb = 0) {
    int W4 = W / 4;
    int f4 = Fin / 4;
    int fshift = 0; while ((1 << fshift) < f4) fshift++;
    int fmask = f4 - 1;
    dim3 grid(cdiv(W4, 256), nodes);
    spmm_kernel<<<grid, 256>>>(W4, fshift, fmask, G / 4, (long)(RS / 4), alpha,
                               (const float4*)in, beta, (const float4*)cin,
                               (float4*)out, (float4*)aux, hi, lo, Kb,
                               cs.cols, cs.vals, cs.nnz, cs.pitch);
}

// ---------------------------------------------------------------------------
// Elementwise kernels
// ---------------------------------------------------------------------------
__global__ void permute_in_kernel(const float* __restrict__ x, float* __restrict__ out,
                                  __nv_bfloat16* __restrict__ hi,
                                  __nv_bfloat16* __restrict__ lo) {
    int g = blockIdx.x * blockDim.x + threadIdx.x;
    if (g >= R3r) return;
    int n = g % 768;
    int t = g / 768;
    int b4 = t / 64, hw = t % 64;
    float v[8];
#pragma unroll
    for (int c = 0; c < 8; c++)
        v[c] = x[(size_t)((b4 * 8 + c) * 64 + hw) * 768 + n];
    long r = (long)n * BATCH + t;
    *(float4*)(out + r * 32)     = make_float4(v[0], v[1], v[2], v[3]);
    *(float4*)(out + r * 32 + 4) = make_float4(v[4], v[5], v[6], v[7]);
    __nv_bfloat16 h[8], l[8];
#pragma unroll
    for (int c = 0; c < 8; c++) {
        h[c] = __float2bfloat16(v[c]);
        l[c] = __float2bfloat16(v[c] - __bfloat162float(h[c]));
    }
    *(uint4*)(hi + r * 32) = *(uint4*)h;
    *(uint4*)(lo + r * 32) = *(uint4*)l;
}

__global__ void permute_out_kernel(const float* __restrict__ y, float* __restrict__ out) {
    int idx = blockIdx.x * blockDim.x + threadIdx.x;
    if (idx >= R3r) return;
    int n = idx % 768;
    int t = idx / 768;
    out[idx] = y[n * BATCH + t];
}

__global__ void pool_kernel(const float* __restrict__ in, float* __restrict__ out,
                            int out_nodes, int F, int G,
                            __nv_bfloat16* __restrict__ hi,
                            __nv_bfloat16* __restrict__ lo) {
    int idx = blockIdx.x * blockDim.x + threadIdx.x;
    int total = out_nodes * BATCH * F;
    if (idx >= total) return;
    int f  = idx % F;
    int rb = idx / F;
    long src    = ((long)((rb / BATCH) * 4) * BATCH + (rb % BATCH)) * F + f;
    long stride = (long)BATCH * F;
    float m = in[src];
    m = fmaxf(m, in[src + stride]);
    m = fmaxf(m, in[src + 2 * stride]);
    m = fmaxf(m, in[src + 3 * stride]);
    long a = (long)rb * G + f;
    out[a] = m;
    __nv_bfloat16 h = __float2bfloat16(m);
    hi[a] = h;
    lo[a] = __float2bfloat16(m - __bfloat162float(h));
}

__global__ void unpool_concat_split_kernel(const float* __restrict__ a,
                                           const float* __restrict__ skip,
                                           __nv_bfloat16* __restrict__ hi,
                                           __nv_bfloat16* __restrict__ lo,
                                           int out_nodes, int Fa, int Fb) {
    int F = Fa + Fb;
    long total = (long)out_nodes * BATCH * F;
    long idx = (long)blockIdx.x * blockDim.x + threadIdx.x;
    if (idx >= total) return;
    int f = (int)(idx % F);
    long r = idx / F;
    int b = (int)(r % BATCH);
    int n = (int)(r / BATCH);
    float v;
    if (f < Fa) v = a[((long)(n / 4) * BATCH + b) * Fa + f];
    else        v = skip[r * Fb + (f - Fa)];
    __nv_bfloat16 h = __float2bfloat16(v);
    hi[idx] = h;
    lo[idx] = __float2bfloat16(v - __bfloat162float(h));
}

// Pack B' (N x 3K) bf16 from fp32 W (K x N): segments [Bhi | Blo | Bhi]
__global__ void pack_b_kernel(const float* __restrict__ W, __nv_bfloat16* __restrict__ Bp,
                              int K, int N, int K3) {
    int idx = blockIdx.x * blockDim.x + threadIdx.x;
    int total = N * K3;
    if (idx >= total) return;
    int q = idx % K3;
    int n = idx / K3;
    int seg = (q >= 2 * K) ? 2 : ((q >= K) ? 1 : 0);
    int k = q - seg * K;
    float w = W[(long)k * N + n];
    __nv_bfloat16 h = __float2bfloat16(w);
    Bp[idx] = (seg == 1) ? __float2bfloat16(w - __bfloat162float(h)) : h;
}

// Clenshaw-pack decoder weights: V (Fin x 4Fout), V0=W0-W2, V1=W1-W3, V2=W2, V3=W3
__global__ void pack_w_kernel(const float* __restrict__ w, float* __restrict__ V,
                              int Fin, int Fout) {
    int idx = blockIdx.x * blockDim.x + threadIdx.x;
    int total = Fin * 4 * Fout;
    if (idx >= total) return;
    int o = idx % Fout;
    int rest = idx / Fout;
    int p = rest % 4;
    int f = rest / 4;
    float v = w[((long)p * Fin + f) * Fout + o];
    if (p == 0) v -= w[((long)2 * Fin + f) * Fout + o];
    if (p == 1) v -= w[((long)3 * Fin + f) * Fout + o];
    V[idx] = v;
}

// ---- BatchNorm in fp32 ----
__global__ void bn_stats_kernel(const float* __restrict__ x, int rows, int F, int ld,
                                int chunks, float* __restrict__ stats) {
    int g = blockIdx.x * blockDim.x + threadIdx.x;
    int total = F * chunks;
    if (g >= total) return;
    int f = g % F;
    int c = g / F;
    float s = 0.f, q = 0.f;
    for (int r = c; r < rows; r += chunks) {
        float v = x[(long)r * ld + f];
        s += v;
        q = fmaf(v, v, q);
    }
    atomicAdd(&stats[f], s);
    atomicAdd(&stats[256 + f], q);
}

__global__ void bn_finalize_kernel(const float* __restrict__ stats, int F, float inv_rows,
                                   const float* __restrict__ gamma,
                                   const float* __restrict__ beta,
                                   float* __restrict__ sc) {
    int f = blockIdx.x * blockDim.x + threadIdx.x;
    if (f >= F) return;
    float mu  = stats[f] * inv_rows;
    float var = stats[256 + f] * inv_rows - mu * mu;
    float scale = gamma[f] * rsqrtf(var + 1e-5f);
    sc[f] = scale;
    sc[256 + f] = beta[f] - mu * scale;
}

__global__ void bn_apply_kernel(float* __restrict__ x, long total, int F, int ld,
                                const float* __restrict__ sc,
                                __nv_bfloat16* __restrict__ hi,
                                __nv_bfloat16* __restrict__ lo) {
    long idx = (long)blockIdx.x * blockDim.x + threadIdx.x;
    if (idx >= total) return;
    int f = (int)(idx % F);
    long r = idx / F;
    long a = r * ld + f;
    float v = fmaf(x[a], sc[f], sc[256 + f]);
    v = v > 0.f ? v : 0.f;
    x[a] = v;
    if (hi) {
        __nv_bfloat16 h = __float2bfloat16(v);
        hi[a] = h;
        lo[a] = __float2bfloat16(v - __bfloat162float(h));
    }
}

__global__ void gemv4_kernel(const float* __restrict__ X, const float* __restrict__ w,
                             int rows, float* __restrict__ u0, float* __restrict__ u1,
                             float* __restrict__ u2, float* __restrict__ u3) {
    __shared__ float ws[128];
    if (threadIdx.x < 128) ws[threadIdx.x] = w[threadIdx.x];
    __syncthreads();
    int r = blockIdx.x * blockDim.x + threadIdx.x;
    if (r >= rows) return;
    const float* xr = X + (long)r * 32;
    float s0 = 0, s1 = 0, s2 = 0, s3 = 0;
#pragma unroll
    for (int f = 0; f < 32; f++) {
        float v = xr[f];
        s0 += v * ws[f];
        s1 += v * ws[32 + f];
        s2 += v * ws[64 + f];
        s3 += v * ws[96 + f];
    }
    u0[r] = s0 - s2; u1[r] = s1 - s3; u2[r] = s2; u3[r] = s3;
}

// ---------------------------------------------------------------------------
// Host-side helpers
// ---------------------------------------------------------------------------
static void run_tc(int M, int N, int K,
                   const __nv_bfloat16* Ahi, const __nv_bfloat16* Alo,
                   const __nv_bfloat16* Bp, float* C, int ldc,
                   int split = 0, float* o0 = nullptr, float* o1 = nullptr,
                   float* o2 = nullptr, float* o3 = nullptr) {
    int K3 = 3 * K;
    if (N % 128 == 0) {
        int sm = 2048 + 2 * (16384 + 16384);
        cudaFuncSetAttribute(tc_gemm<128>, cudaFuncAttributeMaxDynamicSharedMemorySize, sm);
        tc_gemm<128><<<dim3(N / 128, M / 128), 128, sm>>>(M, N, K, K3, Ahi, Alo, Bp,
                                                          C, ldc, split, o0, o1, o2, o3);
    } else if (N == 64) {
        int sm = 2048 + 2 * (16384 + 8192);
        cudaFuncSetAttribute(tc_gemm<64>, cudaFuncAttributeMaxDynamicSharedMemorySize, sm);
        tc_gemm<64><<<dim3(1, M / 128), 128, sm>>>(M, N, K, K3, Ahi, Alo, Bp,
                                                   C, ldc, split, o0, o1, o2, o3);
    } else {
        int sm = 2048 + 2 * (16384 + 4096);
        cudaFuncSetAttribute(tc_gemm<32>, cudaFuncAttributeMaxDynamicSharedMemorySize, sm);
        tc_gemm<32><<<dim3(1, M / 128), 128, sm>>>(M, N, K, K3, Ahi, Alo, Bp,
                                                   C, ldc, split, o0, o1, o2, o3);
    }
}

static void run_bn(float* xbuf, int rows, int F, int ld, const float* gamma,
                   const float* beta, float* statsRegion, float* scRegion,
                   __nv_bfloat16* hi = nullptr, __nv_bfloat16* lo = nullptr) {
    const int chunks = 256;
    bn_stats_kernel<<<cdiv(F * chunks, 256), 256>>>(xbuf, rows, F, ld, chunks, statsRegion);
    bn_finalize_kernel<<<1, 256>>>(statsRegion, F, 1.0f / (float)rows, gamma, beta, scRegion);
    long n = (long)rows * F;
    bn_apply_kernel<<<cdiv(n, 256), 256>>>(xbuf, n, F, ld, scRegion, hi, lo);
}

static void cheb_fill(const Csr& cs, int nodes, int Fin, float* X,
                      __nv_bfloat16* hi, __nv_bfloat16* lo) {
    int W = BATCH * Fin, G = 4 * Fin, RS = BATCH * 4 * Fin;
    long Kb = 4 * Fin;
    run_spmm(cs, nodes, W, Fin, G, RS, 1.f, X, 0.f, nullptr, X + Fin, nullptr,
             hi + Fin, lo + Fin, Kb);
    run_spmm(cs, nodes, W, Fin, G, RS, 2.f, X + Fin, -1.f, X, X + 2 * Fin, nullptr,
             hi + 2 * Fin, lo + 2 * Fin, Kb);
    run_spmm(cs, nodes, W, Fin, G, RS, 2.f, X + 2 * Fin, -1.f, X + Fin, X + 3 * Fin, nullptr,
             hi + 3 * Fin, lo + 3 * Fin, Kb);
}

static void clenshaw_tail(const Csr& cs, int nodes, int F,
                          float* u0, float* u1, float* u2, float* u3) {
    int W = BATCH * F, RS = BATCH * F;
    run_spmm(cs, nodes, W, F, F, RS, 2.f, u3, 1.f, u2, u2, u0);
    run_spmm(cs, nodes, W, F, F, RS, 2.f, u2, 1.f, u1, u1, nullptr);
    run_spmm(cs, nodes, W, F, F, RS, 1.f, u1, 1.f, u0, u0, nullptr);
}

// ---------------------------------------------------------------------------
extern "C" void kernel_launch(void* const* d_in, const int* in_sizes, int n_in,
                              void* d_out, int out_size) {
    const float* x    = (const float*)d_in[0];
    const float* L3   = (const float*)d_in[1];
    const float* L2   = (const float*)d_in[2];
    const float* L1   = (const float*)d_in[3];
    const float* L0   = (const float*)d_in[4];
    const float* w_e3a = (const float*)d_in[5];
    const float* g_e3a = (const float*)d_in[6];
    const float* b_e3a = (const float*)d_in[7];
    const float* w_e3b = (const float*)d_in[8];
    const float* g_e3b = (const float*)d_in[9];
    const float* b_e3b = (const float*)d_in[10];
    const float* w_e2  = (const float*)d_in[11];
    const float* g_e2  = (const float*)d_in[12];
    const float* b_e2  = (const float*)d_in[13];
    const float* w_e1  = (const float*)d_in[14];
    const float* g_e1  = (const float*)d_in[15];
    const float* b_e1  = (const float*)d_in[16];
    const float* w_e0  = (const float*)d_in[17];
    const float* g_e0  = (const float*)d_in[18];
    const float* b_e0  = (const float*)d_in[19];
    const float* w_d1  = (const float*)d_in[20];
    const float* g_d1  = (const float*)d_in[21];
    const float* b_d1  = (const float*)d_in[22];
    const float* w_d2  = (const float*)d_in[23];
    const float* g_d2  = (const float*)d_in[24];
    const float* b_d2  = (const float*)d_in[25];
    const float* w_d3  = (const float*)d_in[26];
    const float* g_d3  = (const float*)d_in[27];
    const float* b_d3  = (const float*)d_in[28];
    const float* w_out = (const float*)d_in[29];

    float* pool = nullptr; float* stats = nullptr; float* bnsc = nullptr;
    int* ccols = nullptr; float* cvals = nullptr; int* cnnz = nullptr;
    __nv_bfloat16 *Ahi = nullptr, *Alo = nullptr, *Bp = nullptr;
    cudaGetSymbolAddress((void**)&pool, g_pool);
    cudaGetSymbolAddress((void**)&stats, g_stats);
    cudaGetSymbolAddress((void**)&bnsc, g_bnsc);
    cudaGetSymbolAddress((void**)&ccols, g_ccols);
    cudaGetSymbolAddress((void**)&cvals, g_cvals);
    cudaGetSymbolAddress((void**)&cnnz, g_cnnz);
    cudaGetSymbolAddress((void**)&Ahi, g_ahi);
    cudaGetSymbolAddress((void**)&Alo, g_alo);
    cudaGetSymbolAddress((void**)&Bp, g_bp);

    float* S3 = pool + OFF_S3;
    float* S2 = pool + OFF_S2;
    float* S1 = pool + OFF_S1;
    float* XA = pool + OFF_XA;
    float* XB = pool + OFF_XB;
    float* X2 = pool + OFF_X2;
    float* X1 = pool + OFF_X1;
    float* X0 = pool + OFF_X0;
    float* T0 = pool + OFF_T0;
    float* T1 = pool + OFF_T1;
    float* T2 = pool + OFF_T2;
    float* T3 = pool + OFF_T3;
    float* U  = pool + OFF_U;
    float* Vw = pool + OFF_W;

    Csr cs3 = { ccols,                cvals,                cnnz,                N3 };
    Csr cs2 = { ccols + C3,           cvals + C3,           cnnz + N3,           N2 };
    Csr cs1 = { ccols + C3 + C2,      cvals + C3 + C2,      cnnz + N3 + N2,      N1 };
    Csr cs0 = { ccols + C3 + C2 + C1, cvals + C3 + C2 + C1, cnnz + N3 + N2 + N1, N0 };

    cudaMemsetAsync(stats, 0, 4096 * sizeof(float));

    build_csr_kernel<<<cdiv(N3, 8), 256>>>(L3, N3, (int*)cs3.cols, (float*)cs3.vals, (int*)cs3.nnz);
    build_csr_kernel<<<cdiv(N2, 8), 256>>>(L2, N2, (int*)cs2.cols, (float*)cs2.vals, (int*)cs2.nnz);
    build_csr_kernel<<<cdiv(N1, 8), 256>>>(L1, N1, (int*)cs1.cols, (float*)cs1.vals, (int*)cs1.nnz);
    build_csr_kernel<<<cdiv(N0, 8), 256>>>(L0, N0, (int*)cs0.cols, (float*)cs0.vals, (int*)cs0.nnz);

    // ---- input permute -> XA block0 (G=32) + bf16 (K=32) ----
    permute_in_kernel<<<cdiv(R3r, 256), 256>>>(x, XA, Ahi, Alo);

    // ---- e3a ----
    cheb_fill(cs3, N3, 8, XA, Ahi, Alo);
    pack_b_kernel<<<cdiv(32 * 96, 256), 256>>>(w_e3a, Bp, 32, 32, 96);
    run_tc(R3r, 32, 32, Ahi, Alo, Bp, XB, 128);
    run_bn(XB, R3r, 32, 128, g_e3a, b_e3a, stats, bnsc, Ahi, Alo);

    // ---- e3b ----
    cheb_fill(cs3, N3, 32, XB, Ahi, Alo);
    pack_b_kernel<<<cdiv(64 * 384, 256), 256>>>(w_e3b, Bp, 128, 64, 384);
    run_tc(R3r, 64, 128, Ahi, Alo, Bp, S3, 64);
    run_bn(S3, R3r, 64, 64, g_e3b, b_e3b, stats + 512, bnsc + 512);

    // ---- e2 ----
    pool_kernel<<<cdiv((long)R2r * 64, 256), 256>>>(S3, X2, N2, 64, 256, Ahi, Alo);
    cheb_fill(cs2, N2, 64, X2, Ahi, Alo);
    pack_b_kernel<<<cdiv(128 * 768, 256), 256>>>(w_e2, Bp, 256, 128, 768);
    run_tc(R2r, 128, 256, Ahi, Alo, Bp, S2, 128);
    run_bn(S2, R2r, 128, 128, g_e2, b_e2, stats + 1024, bnsc + 1024);

    // ---- e1 ----
    pool_kernel<<<cdiv((long)R1r * 128, 256), 256>>>(S2, X1, N1, 128, 512, Ahi, Alo);
    cheb_fill(cs1, N1, 128, X1, Ahi, Alo);
    pack_b_kernel<<<cdiv(256 * 1536, 256), 256>>>(w_e1, Bp, 512, 256, 1536);
    run_tc(R1r, 256, 512, Ahi, Alo, Bp, S1, 256);
    run_bn(S1, R1r, 256, 256, g_e1, b_e1, stats + 1536, bnsc + 1536);

    // ---- e0 ----
    pool_kernel<<<cdiv((long)R0r * 256, 256), 256>>>(S1, X0, N0, 256, 1024, Ahi, Alo);
    cheb_fill(cs0, N0, 256, X0, Ahi, Alo);
    pack_b_kernel<<<cdiv(256 * 3072, 256), 256>>>(w_e0, Bp, 1024, 256, 3072);
    run_tc(R0r, 256, 1024, Ahi, Alo, Bp, T0, 256);
    run_bn(T0, R0r, 256, 256, g_e0, b_e0, stats + 2048, bnsc + 2048);

    // ---- d1 ----
    unpool_concat_split_kernel<<<cdiv((long)R1r * 512, 256), 256>>>(T0, S1, Ahi, Alo, N1, 256, 256);
    pack_w_kernel<<<cdiv(512 * 512, 256), 256>>>(w_d1, Vw, 512, 128);
    pack_b_kernel<<<cdiv(512 * 1536, 256), 256>>>(Vw, Bp, 512, 512, 1536);
    run_tc(R1r, 512, 512, Ahi, Alo, Bp, nullptr, 0, 128, T0, T1, T2, T3);
    clenshaw_tail(cs1, N1, 128, T0, T1, T2, T3);
    run_bn(T0, R1r, 128, 128, g_d1, b_d1, stats + 2560, bnsc + 2560);

    // ---- d2 ----
    unpool_concat_split_kernel<<<cdiv((long)R2r * 256, 256), 256>>>(T0, S2, Ahi, Alo, N2, 128, 128);
    pack_w_kernel<<<cdiv(256 * 256, 256), 256>>>(w_d2, Vw, 256, 64);
    pack_b_kernel<<<cdiv(256 * 768, 256), 256>>>(Vw, Bp, 256, 256, 768);
    run_tc(R2r, 256, 256, Ahi, Alo, Bp, nullptr, 0, 64, T0, T1, T2, T3);
    clenshaw_tail(cs2, N2, 64, T0, T1, T2, T3);
    run_bn(T0, R2r, 64, 64, g_d2, b_d2, stats + 3072, bnsc + 3072);

    // ---- d3 ----
    unpool_concat_split_kernel<<<cdiv((long)R3r * 128, 256), 256>>>(T0, S3, Ahi, Alo, N3, 64, 64);
    pack_w_kernel<<<cdiv(128 * 128, 256), 256>>>(w_d3, Vw, 128, 32);
    pack_b_kernel<<<cdiv(128 * 384, 256), 256>>>(Vw, Bp, 128, 128, 384);
    run_tc(R3r, 128, 128, Ahi, Alo, Bp, nullptr, 0, 32, T0, T1, T2, T3);
    clenshaw_tail(cs3, N3, 32, T0, T1, T2, T3);
    run_bn(T0, R3r, 32, 32, g_d3, b_d3, stats + 3584, bnsc + 3584);

    // ---- output conv (Fout=1) ----
    float* u0 = U;
    float* u1 = U + R3r;
    float* u2 = U + 2 * (long)R3r;
    float* u3 = U + 3 * (long)R3r;
    gemv4_kernel<<<cdiv(R3r, 256), 256>>>(T0, w_out, R3r, u0, u1, u2, u3);
    run_spmm(cs3, N3, 256, 256, 256, 256, 2.f, u3, 1.f, u2, u2, u0);
    run_spmm(cs3, N3, 256, 256, 256, 256, 2.f, u2, 1.f, u1, u1, nullptr);
    run_spmm(cs3, N3, 256, 256, 256, 256, 1.f, u1, 1.f, u0, u0, nullptr);

    permute_out_kernel<<<cdiv(R3r, 256), 256>>>(u0, (float*)d_out);
}